// round 1
// baseline (speedup 1.0000x reference)
#include <cuda_runtime.h>
#include <math.h>
#include <stdint.h>

#define Kdim 256
#define Tdim 64
#define Ddim 64
#define Hdim 256
#define Jdim 2016                  // 64*63/2
#define KJ   (Kdim*Jdim)           // 516096
#define TJ   32                    // pairs per block (main kernel)
#define HS_STRIDE 36               // padded stride (words) for H tile: conflict-free + 16B aligned

// Scratch (device globals — no allocation allowed)
__device__ float g_P[Kdim*Tdim*Hdim];   // 16.8 MB: emb @ W1[:64]  + b1
__device__ float g_Q[Kdim*Tdim*Hdim];   // 16.8 MB: emb @ W1[64:]
__device__ int2  g_pairs[Jdim];

// ---------------------------------------------------------------------------
// Kernel 1: triu pair table (row-major triu order, matching np.triu_indices)
// ---------------------------------------------------------------------------
__global__ void pairs_kernel() {
    int i = threadIdx.x;
    if (i < Tdim - 1) {
        int start = i * (Tdim - 1) - i * (i - 1) / 2;
        for (int j = i + 1; j < Tdim; j++) g_pairs[start++] = make_int2(i, j);
    }
}

// ---------------------------------------------------------------------------
// Kernel 2: P/Q precompute. Block = 256 threads, 16 rows. grid = 1024.
// P[row][c] = sum_d emb[row][d]*W1[d][c] + b1[c];  Q uses W1[64+d][c].
// ---------------------------------------------------------------------------
__global__ void __launch_bounds__(256) pq_kernel(const float* __restrict__ emb,
                                                 const float* __restrict__ W1,
                                                 const float* __restrict__ b1) {
    __shared__ float es[16][64];
    int row0 = blockIdx.x * 16;
    int tid = threadIdx.x;
#pragma unroll
    for (int q = 0; q < 4; q++) {
        int v = tid + q * 256;                      // 1024 floats total
        es[v >> 6][v & 63] = emb[row0 * 64 + v];
    }
    __syncthreads();
    int c = tid;                                    // output channel 0..255
    float accP[16], accQ[16];
#pragma unroll
    for (int r = 0; r < 16; r++) { accP[r] = 0.f; accQ[r] = 0.f; }
#pragma unroll 2
    for (int d = 0; d < 64; d++) {
        float wa = W1[d * 256 + c];
        float wb = W1[(64 + d) * 256 + c];
#pragma unroll
        for (int r = 0; r < 16; r++) {
            float e = es[r][d];
            accP[r] = fmaf(e, wa, accP[r]);
            accQ[r] = fmaf(e, wb, accQ[r]);
        }
    }
    float bb = b1[c];
#pragma unroll
    for (int r = 0; r < 16; r++) {
        g_P[(row0 + r) * 256 + c] = accP[r] + bb;
        g_Q[(row0 + r) * 256 + c] = accQ[r];
    }
}

// ---------------------------------------------------------------------------
// Kernel 3: main. Block = (tile of 32 pairs) x (one k). grid = (63, 256).
// Phase 1: H[kk][m] = relu(P[k,i1]+Q[k,i2]) into smem (stride 36).
// Phase 2: emb_out[m][d] = sum_kk H[kk][m]*W2[kk][d] + b2[d]  (packed f32x2).
// Phase 3: branch norms via warp shfl reduction.
// ---------------------------------------------------------------------------
extern __shared__ float sm[];

__device__ __forceinline__ void ffma2(unsigned long long& acc,
                                      unsigned long long h,
                                      unsigned long long w) {
    asm("fma.rn.f32x2 %0, %1, %2, %0;" : "+l"(acc) : "l"(h), "l"(w));
}

__global__ void __launch_bounds__(256) main_kernel(const float* __restrict__ embg,
                                                   const float* __restrict__ W2,
                                                   const float* __restrict__ b2g,
                                                   float* __restrict__ out) {
    float* W2s = sm;                 // 16384 floats (64 KB): W2[kk][d]
    float* Hs  = sm + 16384;         // 256*36 floats: Hs[kk*36 + m]
    __shared__ int i1s[TJ], i2s[TJ];

    int tid  = threadIdx.x;
    int tile = blockIdx.x;
    int k    = blockIdx.y;

    // Load W2 into smem (float4, coalesced)
    const float4* W2v = (const float4*)W2;
    float4* W2sv = (float4*)W2s;
#pragma unroll
    for (int q = 0; q < 16; q++) {
        int v = tid + q * 256;       // 4096 float4 total
        W2sv[v] = W2v[v];
    }
    if (tid < TJ) {
        int2 p = g_pairs[tile * TJ + tid];
        i1s[tid] = p.x; i2s[tid] = p.y;
    }
    __syncthreads();

    // -------- Phase 1: build H tile --------
    {
        int c = tid;                                  // kk channel
        const float* Pk = g_P + (size_t)k * Tdim * 256;
        const float* Qk = g_Q + (size_t)k * Tdim * 256;
#pragma unroll
        for (int q = 0; q < 8; q++) {
            float4 v;
            float* vv = (float*)&v;
#pragma unroll
            for (int s = 0; s < 4; s++) {
                int m = q * 4 + s;
                float h = Pk[i1s[m] * 256 + c] + Qk[i2s[m] * 256 + c];
                vv[s] = fmaxf(h, 0.f);
            }
            *(float4*)&Hs[c * HS_STRIDE + q * 4] = v;
        }
    }
    __syncthreads();

    // -------- Phase 2: GEMM (32 pairs x 64 d over kk=256), packed f32x2 --------
    int d  = tid & 63;
    int mg = tid >> 6;                                // 0..3 -> m block of 8
    unsigned long long acc0 = 0, acc1 = 0, acc2 = 0, acc3 = 0;
    const unsigned long long* Hp = (const unsigned long long*)Hs;
#pragma unroll 4
    for (int kk = 0; kk < 256; kk++) {
        float w = W2s[kk * 64 + d];
        unsigned long long ww;
        asm("mov.b64 %0, {%1, %2};" : "=l"(ww) : "f"(w), "f"(w));
        const ulonglong2* hp = (const ulonglong2*)(Hp + kk * (HS_STRIDE / 2) + mg * 4);
        ulonglong2 h01 = hp[0];
        ulonglong2 h23 = hp[1];
        ffma2(acc0, h01.x, ww);
        ffma2(acc1, h01.y, ww);
        ffma2(acc2, h23.x, ww);
        ffma2(acc3, h23.y, ww);
    }
    __syncthreads();   // everyone done reading Hs — safe to reuse as Es

    // -------- Epilogue: bias, write embedding, stash in smem --------
    float2 a[4];
    asm("mov.b64 {%0,%1}, %2;" : "=f"(a[0].x), "=f"(a[0].y) : "l"(acc0));
    asm("mov.b64 {%0,%1}, %2;" : "=f"(a[1].x), "=f"(a[1].y) : "l"(acc1));
    asm("mov.b64 {%0,%1}, %2;" : "=f"(a[2].x), "=f"(a[2].y) : "l"(acc2));
    asm("mov.b64 {%0,%1}, %2;" : "=f"(a[3].x), "=f"(a[3].y) : "l"(acc3));
    float bb = b2g[d];
    int jbase = k * Jdim + tile * TJ;
    float* out_emb = out + 4ull * KJ;
    float* Es = Hs;                                   // 32*64 floats, reuse
#pragma unroll
    for (int p = 0; p < 4; p++) {
        int m = mg * 8 + p * 2;
        float e0 = a[p].x + bb;
        float e1 = a[p].y + bb;
        out_emb[(size_t)(jbase + m)     * 64 + d] = e0;
        out_emb[(size_t)(jbase + m + 1) * 64 + d] = e1;
        Es[m * 64 + d]       = e0;
        Es[(m + 1) * 64 + d] = e1;
    }
    __syncthreads();

    // -------- Phase 3: branch norms. Warp w handles pairs m = w*4..w*4+3 --------
    int lane = tid & 31, w = tid >> 5;
    const float* embk = embg + (size_t)k * Tdim * Ddim;
#pragma unroll
    for (int q = 0; q < 4; q++) {
        int m  = w * 4 + q;
        int a1 = i1s[m], a2 = i2s[m];
        float e0 = Es[m * 64 + lane];
        float e1 = Es[m * 64 + lane + 32];
        float x0 = embk[a1 * 64 + lane]      - e0;
        float x1 = embk[a1 * 64 + lane + 32] - e1;
        float y0 = embk[a2 * 64 + lane]      - e0;
        float y1 = embk[a2 * 64 + lane + 32] - e1;
        float s1 = x0 * x0 + x1 * x1;
        float s2 = y0 * y0 + y1 * y1;
#pragma unroll
        for (int off = 16; off; off >>= 1) {
            s1 += __shfl_xor_sync(0xffffffff, s1, off);
            s2 += __shfl_xor_sync(0xffffffff, s2, off);
        }
        if (lane == 0) {
            out[2ull * KJ + jbase + m] = sqrtf(s1);
            out[3ull * KJ + jbase + m] = sqrtf(s2);
        }
    }
}

// ---------------------------------------------------------------------------
// Kernel 4: trivial outputs: idx1, idx2 (as float), log_v_plus = 0
// ---------------------------------------------------------------------------
__global__ void fill_kernel(float* __restrict__ out) {
    int j = blockIdx.x * 256 + threadIdx.x;
    int k = blockIdx.y;
    if (j < Jdim) {
        int2 p = g_pairs[j];
        size_t base = (size_t)k * Jdim + j;
        out[base]            = (float)p.x;
        out[KJ + base]       = (float)p.y;
        out[68ull * KJ + base] = 0.f;
    }
}

// ---------------------------------------------------------------------------
extern "C" void kernel_launch(void* const* d_in, const int* in_sizes, int n_in,
                              void* d_out, int out_size) {
    // Identify inputs by element count (dict order: N, emb, hashes, W1, b1, W2, b2).
    // 16384 appears twice (hashes int64, W2 fp32) — last occurrence is W2.
    const float *emb = 0, *W1 = 0, *b1 = 0, *W2 = 0, *b2 = 0;
    for (int i = 0; i < n_in; i++) {
        int s = in_sizes[i];
        if      (s == Kdim * Tdim * Ddim) emb = (const float*)d_in[i];
        else if (s == 2 * Ddim * Hdim)    W1  = (const float*)d_in[i];
        else if (s == Hdim)               b1  = (const float*)d_in[i];
        else if (s == Ddim)               b2  = (const float*)d_in[i];
        else if (s == Hdim * Ddim)        W2  = (const float*)d_in[i];  // last wins
    }
    float* out = (float*)d_out;

    pairs_kernel<<<1, 64>>>();
    pq_kernel<<<(Kdim * Tdim) / 16, 256>>>(emb, W1, b1);

    const int smem_bytes = (16384 + 256 * HS_STRIDE) * sizeof(float);  // 102400
    cudaFuncSetAttribute(main_kernel, cudaFuncAttributeMaxDynamicSharedMemorySize, smem_bytes);
    main_kernel<<<dim3(Jdim / TJ, Kdim), 256, smem_bytes>>>(emb, W2, b2, out);

    fill_kernel<<<dim3((Jdim + 255) / 256, Kdim), 256>>>(out);
}

// round 2
// speedup vs baseline: 1.1310x; 1.1310x over previous
#include <cuda_runtime.h>
#include <math.h>
#include <stdint.h>

#define Kdim 256
#define Tdim 64
#define Ddim 64
#define Hdim 256
#define Jdim 2016                  // 64*63/2
#define KJ   (Kdim*Jdim)           // 516096
#define TJ   32                    // pairs per tile
#define TILES_PER_K 63             // 2016/32
#define NTILES (Kdim*TILES_PER_K)  // 16128
#define HS_STRIDE 36               // padded word stride for H tile
#define GRID_MAIN 296              // 148 SMs x 2 blocks

// Scratch (device globals — no allocation allowed)
__device__ float g_P[Kdim*Tdim*Hdim];   // 16.8 MB: emb @ W1[:64] + b1
__device__ float g_Q[Kdim*Tdim*Hdim];   // 16.8 MB: emb @ W1[64:]
__device__ int2  g_pairs[Jdim];

// ---------------------------------------------------------------------------
// Kernel 1: P/Q precompute (+ pair table generated by block 0).
// Block = 256 threads, 16 rows. grid = 1024.
// ---------------------------------------------------------------------------
__global__ void __launch_bounds__(256) pq_kernel(const float* __restrict__ emb,
                                                 const float* __restrict__ W1,
                                                 const float* __restrict__ b1) {
    if (blockIdx.x == 0 && threadIdx.x < Tdim - 1) {
        int i = threadIdx.x;
        int start = i * (Tdim - 1) - i * (i - 1) / 2;
        for (int j = i + 1; j < Tdim; j++) g_pairs[start++] = make_int2(i, j);
    }
    __shared__ float es[16][64];
    int row0 = blockIdx.x * 16;
    int tid = threadIdx.x;
#pragma unroll
    for (int q = 0; q < 4; q++) {
        int v = tid + q * 256;
        es[v >> 6][v & 63] = emb[row0 * 64 + v];
    }
    __syncthreads();
    int c = tid;
    float accP[16], accQ[16];
#pragma unroll
    for (int r = 0; r < 16; r++) { accP[r] = 0.f; accQ[r] = 0.f; }
#pragma unroll 2
    for (int d = 0; d < 64; d++) {
        float wa = W1[d * 256 + c];
        float wb = W1[(64 + d) * 256 + c];
#pragma unroll
        for (int r = 0; r < 16; r++) {
            float e = es[r][d];
            accP[r] = fmaf(e, wa, accP[r]);
            accQ[r] = fmaf(e, wb, accQ[r]);
        }
    }
    float bb = b1[c];
#pragma unroll
    for (int r = 0; r < 16; r++) {
        g_P[(row0 + r) * 256 + c] = accP[r] + bb;
        g_Q[(row0 + r) * 256 + c] = accQ[r];
    }
}

// ---------------------------------------------------------------------------
// Kernel 2: persistent main. grid = 296 blocks x 256 threads.
// Each block loads W2 into smem ONCE, then loops over (k, tile) work items.
// Per tile: phase1 H=relu(P+Q) -> smem; phase2 packed-f32x2 GEMM;
// epilogue embedding + idx/logv; phase3 branch norms.
// ---------------------------------------------------------------------------
extern __shared__ float sm[];

__device__ __forceinline__ void ffma2(unsigned long long& acc,
                                      unsigned long long h,
                                      unsigned long long w) {
    asm("fma.rn.f32x2 %0, %1, %2, %0;" : "+l"(acc) : "l"(h), "l"(w));
}

__global__ void __launch_bounds__(256, 2) main_kernel(const float* __restrict__ embg,
                                                      const float* __restrict__ W2,
                                                      const float* __restrict__ b2g,
                                                      float* __restrict__ out) {
    float* W2s = sm;                 // 16384 floats (64 KB)
    float* Hs  = sm + 16384;         // 256*36 floats
    __shared__ int i1s[TJ], i2s[TJ];

    int tid = threadIdx.x;

    // Load W2 once per block
    {
        const float4* W2v = (const float4*)W2;
        float4* W2sv = (float4*)W2s;
#pragma unroll
        for (int q = 0; q < 16; q++) W2sv[tid + q * 256] = W2v[tid + q * 256];
    }

    int d  = tid & 63;
    int mg = tid >> 6;
    float bb = b2g[d];
    int lane = tid & 31, w = tid >> 5;
    float* out_emb = out + 4ull * KJ;

    for (int item = blockIdx.x; item < NTILES; item += GRID_MAIN) {
        int k    = item / TILES_PER_K;
        int tile = item - k * TILES_PER_K;
        int jbase = k * Jdim + tile * TJ;

        __syncthreads();             // previous tile's Hs/i1s consumers done
        if (tid < TJ) {
            int2 p = g_pairs[tile * TJ + tid];
            i1s[tid] = p.x; i2s[tid] = p.y;
            // trivial outputs folded in here
            out[(size_t)jbase + tid]             = (float)p.x;
            out[KJ + (size_t)jbase + tid]        = (float)p.y;
            out[68ull * KJ + (size_t)jbase + tid] = 0.f;
        }
        __syncthreads();

        // -------- Phase 1: build H tile --------
        {
            int c = tid;
            const float* Pk = g_P + (size_t)k * Tdim * 256;
            const float* Qk = g_Q + (size_t)k * Tdim * 256;
#pragma unroll
            for (int q = 0; q < 8; q++) {
                float4 v;
                float* vv = (float*)&v;
#pragma unroll
                for (int s = 0; s < 4; s++) {
                    int m = q * 4 + s;
                    float h = Pk[i1s[m] * 256 + c] + Qk[i2s[m] * 256 + c];
                    vv[s] = fmaxf(h, 0.f);
                }
                *(float4*)&Hs[c * HS_STRIDE + q * 4] = v;
            }
        }
        __syncthreads();

        // -------- Phase 2: GEMM 32 pairs x 64 d over kk=256 (packed f32x2) --------
        unsigned long long acc0 = 0, acc1 = 0, acc2 = 0, acc3 = 0;
        const unsigned long long* Hp = (const unsigned long long*)Hs;
#pragma unroll 4
        for (int kk = 0; kk < 256; kk++) {
            float wv = W2s[kk * 64 + d];
            unsigned long long ww;
            asm("mov.b64 %0, {%1, %2};" : "=l"(ww) : "f"(wv), "f"(wv));
            const ulonglong2* hp = (const ulonglong2*)(Hp + kk * (HS_STRIDE / 2) + mg * 4);
            ulonglong2 h01 = hp[0];
            ulonglong2 h23 = hp[1];
            ffma2(acc0, h01.x, ww);
            ffma2(acc1, h01.y, ww);
            ffma2(acc2, h23.x, ww);
            ffma2(acc3, h23.y, ww);
        }
        __syncthreads();             // Hs fully read -> reuse as Es

        // -------- Epilogue: bias, write embedding, stash Es --------
        float2 a[4];
        asm("mov.b64 {%0,%1}, %2;" : "=f"(a[0].x), "=f"(a[0].y) : "l"(acc0));
        asm("mov.b64 {%0,%1}, %2;" : "=f"(a[1].x), "=f"(a[1].y) : "l"(acc1));
        asm("mov.b64 {%0,%1}, %2;" : "=f"(a[2].x), "=f"(a[2].y) : "l"(acc2));
        asm("mov.b64 {%0,%1}, %2;" : "=f"(a[3].x), "=f"(a[3].y) : "l"(acc3));
        float* Es = Hs;
#pragma unroll
        for (int p = 0; p < 4; p++) {
            int m = mg * 8 + p * 2;
            float e0 = a[p].x + bb;
            float e1 = a[p].y + bb;
            out_emb[(size_t)(jbase + m)     * 64 + d] = e0;
            out_emb[(size_t)(jbase + m + 1) * 64 + d] = e1;
            Es[m * 64 + d]       = e0;
            Es[(m + 1) * 64 + d] = e1;
        }
        __syncthreads();

        // -------- Phase 3: branch norms (warp w -> pairs w*4..w*4+3) --------
        const float* embk = embg + (size_t)k * Tdim * Ddim;
#pragma unroll
        for (int q = 0; q < 4; q++) {
            int m  = w * 4 + q;
            int a1 = i1s[m], a2 = i2s[m];
            float e0 = Es[m * 64 + lane];
            float e1 = Es[m * 64 + lane + 32];
            float x0 = embk[a1 * 64 + lane]      - e0;
            float x1 = embk[a1 * 64 + lane + 32] - e1;
            float y0 = embk[a2 * 64 + lane]      - e0;
            float y1 = embk[a2 * 64 + lane + 32] - e1;
            float s1 = x0 * x0 + x1 * x1;
            float s2 = y0 * y0 + y1 * y1;
#pragma unroll
            for (int off = 16; off; off >>= 1) {
                s1 += __shfl_xor_sync(0xffffffff, s1, off);
                s2 += __shfl_xor_sync(0xffffffff, s2, off);
            }
            if (lane == 0) {
                out[2ull * KJ + jbase + m] = sqrtf(s1);
                out[3ull * KJ + jbase + m] = sqrtf(s2);
            }
        }
    }
}

// ---------------------------------------------------------------------------
extern "C" void kernel_launch(void* const* d_in, const int* in_sizes, int n_in,
                              void* d_out, int out_size) {
    const float *emb = 0, *W1 = 0, *b1 = 0, *W2 = 0, *b2 = 0;
    for (int i = 0; i < n_in; i++) {
        int s = in_sizes[i];
        if      (s == Kdim * Tdim * Ddim) emb = (const float*)d_in[i];
        else if (s == 2 * Ddim * Hdim)    W1  = (const float*)d_in[i];
        else if (s == Hdim)               b1  = (const float*)d_in[i];
        else if (s == Ddim)               b2  = (const float*)d_in[i];
        else if (s == Hdim * Ddim)        W2  = (const float*)d_in[i];  // last wins
    }
    float* out = (float*)d_out;

    pq_kernel<<<(Kdim * Tdim) / 16, 256>>>(emb, W1, b1);

    const int smem_bytes = (16384 + 256 * HS_STRIDE) * sizeof(float);  // 102400
    cudaFuncSetAttribute(main_kernel, cudaFuncAttributeMaxDynamicSharedMemorySize, smem_bytes);
    main_kernel<<<GRID_MAIN, 256, smem_bytes>>>(emb, W2, b2, out);
}